// round 17
// baseline (speedup 1.0000x reference)
#include <cuda_runtime.h>
#include <cuda_fp16.h>
#include <cstdint>

// EdgeNetwork via single-piece fp16 mma.sync m16n8k16.
// H = E@W + b ; messages[g,i] = sum_j relu(H[g, 32i+j]) * s[g,j]
// E, W rounded to fp16 (rel err ~3e-4 << 1e-3); accum + epilogue fp32.
// R17: 4 CTAs/SM at 64 regs — W+bias fragments served from smem (conflict-free
// LDS.64 per tile), quad-shuffle reduce + pitch-17 OSM, R14 main loop otherwise.

#define NTHREADS 256

// dynamic smem offsets (bytes)
#define SM_EH   0                        // uint2[512]          4 KB
#define SM_SP   4096                     // float2[2048]       16 KB
#define SM_W    20480                    // uint2[2048]        16 KB
#define SM_BS   36864                    // float[512]          2 KB
#define SM_OSM  38912                    // float[128*17]    8704 B
#define SM_TOTAL (38912 + 8704)          // 47616 B/CTA (x4 = 186 KB/SM)

// fp16 W, fragment-permuted:
// d_Wh[n*4+q] = { h2(w[2q][n],w[2q+1][n]), h2(w[2q+8][n],w[2q+9][n]) }
__device__ uint2 d_Wh[4096];

__device__ __forceinline__ uint32_t pack_h2f(float a, float b) {
    __half2 h = __floats2half2_rn(a, b);
    return *reinterpret_cast<uint32_t*>(&h);
}

__global__ void prep_w(const float* __restrict__ W) {
    int idx = blockIdx.x * 256 + threadIdx.x;   // 0..4095 over [n][q]
    int n = idx >> 2, q = idx & 3;
    d_Wh[idx] = make_uint2(
        pack_h2f(W[(2 * q)     * 1024 + n], W[(2 * q + 1) * 1024 + n]),
        pack_h2f(W[(2 * q + 8) * 1024 + n], W[(2 * q + 9) * 1024 + n]));
}

// D = A*B + {cx,cy,cx,cy}
__device__ __forceinline__ void mma16c(float* d, uint32_t a0, uint32_t a1,
                                       uint32_t a2, uint32_t a3,
                                       uint32_t b0, uint32_t b1,
                                       float cx, float cy) {
    asm volatile(
        "mma.sync.aligned.m16n8k16.row.col.f32.f16.f16.f32 "
        "{%0,%1,%2,%3}, {%4,%5,%6,%7}, {%8,%9}, {%10,%11,%10,%11};"
        : "=f"(d[0]), "=f"(d[1]), "=f"(d[2]), "=f"(d[3])
        : "r"(a0), "r"(a1), "r"(a2), "r"(a3), "r"(b0), "r"(b1),
          "f"(cx), "f"(cy));
}

__global__ __launch_bounds__(NTHREADS, 4) void edge_net_mma(
    const float* __restrict__ states,
    const float* __restrict__ edges,
    const float* __restrict__ bg,
    float* __restrict__ out)
{
    extern __shared__ char sm[];
    uint2*  EH  = (uint2*)(sm + SM_EH);      // [row][q]
    float2* SP  = (float2*)(sm + SM_SP);     // [a][row][q2]
    uint2*  WSM = (uint2*)(sm + SM_W);       // [n_local][q]
    float*  BS  = (float*)(sm + SM_BS);      // bias slice
    float*  OSM = (float*)(sm + SM_OSM);     // [row][il], pitch 17

    const int tid = threadIdx.x;
    const int eb = blockIdx.x & 511;         // edge block (128 edges)
    const int cb = blockIdx.x >> 9;          // column half (512 cols)
    const int gbase = eb * 128;
    const int col0 = cb * 512;

    const int w = tid >> 5, lane = tid & 31;
    const int g = lane >> 2;                 // groupID: row-in-tile / B-col
    const int q = lane & 3;                  // threadID-in-group

    // ---- Stage W slice + bias slice (contiguous, L2-resident) ----
    {
        const uint4* srcW = (const uint4*)(d_Wh + col0 * 4);
        uint4* dstW = (uint4*)WSM;
        #pragma unroll
        for (int k = 0; k < 4; k++)
            dstW[tid + k * 256] = srcW[tid + k * 256];
        BS[tid] = bg[col0 + tid];
        BS[tid + 256] = bg[col0 + tid + 256];
    }
    // ---- Stage edges as fp16 fragments ----
    {
        const float2* er = (const float2*)(edges + (size_t)gbase * 16);
        #pragma unroll
        for (int k = 0; k < 2; k++) {
            int item = tid + k * 256;        // 0..511 over [row][q]
            int row = item >> 2, qq = item & 3;
            float2 v0 = er[row * 8 + qq];
            float2 v1 = er[row * 8 + qq + 4];
            EH[item] = make_uint2(pack_h2f(v0.x, v0.y), pack_h2f(v1.x, v1.y));
        }
    }
    // ---- Stage states: SP[a][row][q2] = {s[row][8a+2q2], s[row][8a+2q2+1]} ----
    {
        const float4* sv = (const float4*)(states + (size_t)gbase * 32);
        #pragma unroll
        for (int k = 0; k < 4; k++) {
            int idx = tid + k * 256;         // 0..1023 over [row][f4]
            int row = idx >> 3, f4 = idx & 7;
            float4 v = sv[idx];
            int a = f4 >> 1, q2 = (f4 & 1) * 2;
            *(float4*)((float*)SP + ((a * 128 + row) * 4 + q2) * 2) = v;
        }
    }
    __syncthreads();

    // ---- Main: 8 rolled steps of 16 rows ----
    #pragma unroll 1
    for (int hp = 0; hp < 8; hp++) {
        const int rb = hp * 16;

        const uint2 aA = EH[(rb + g) * 4 + q];        // rows g
        const uint2 aB = EH[(rb + 8 + g) * 4 + q];    // rows g+8

        float mm[2][2] = {{0.f, 0.f}, {0.f, 0.f}};    // [ip][row-half]

        #pragma unroll
        for (int a = 0; a < 4; a++) {
            const float2 s0 = SP[a * 512 + (rb + g) * 4 + q];
            const float2 s1 = SP[a * 512 + (rb + 8 + g) * 4 + q];

            #pragma unroll
            for (int ip = 0; ip < 2; ip++) {
                const int ct = ip * 4 + a;
                const int nl = w * 64 + ct * 8 + g;
                const uint2 wf = WSM[nl * 4 + q];               // conflict-free LDS.64
                const float2 bf = *(const float2*)(BS + w * 64 + ct * 8 + 2 * q);
                float d[4];
                mma16c(d, aA.x, aB.x, aA.y, aB.y, wf.x, wf.y, bf.x, bf.y);

                mm[ip][0] = fmaf(fmaxf(d[0], 0.f), s0.x, mm[ip][0]);
                mm[ip][0] = fmaf(fmaxf(d[1], 0.f), s0.y, mm[ip][0]);
                mm[ip][1] = fmaf(fmaxf(d[2], 0.f), s1.x, mm[ip][1]);
                mm[ip][1] = fmaf(fmaxf(d[3], 0.f), s1.y, mm[ip][1]);
            }
        }

        // ---- Quad reduce, stage to OSM (pitch 17, conflict-free) ----
        #pragma unroll
        for (int ip = 0; ip < 2; ip++) {
            const int il = w * 2 + ip;       // local column 0..15
            float v0 = mm[ip][0], v1 = mm[ip][1];
            v0 += __shfl_xor_sync(0xffffffffu, v0, 1);
            v0 += __shfl_xor_sync(0xffffffffu, v0, 2);
            v1 += __shfl_xor_sync(0xffffffffu, v1, 1);
            v1 += __shfl_xor_sync(0xffffffffu, v1, 2);
            if (q == 0) {
                OSM[(rb + g) * 17 + il] = v0;
                OSM[(rb + 8 + g) * 17 + il] = v1;
            }
        }
    }

    // ---- Coalesced flush ----
    __syncthreads();
    #pragma unroll
    for (int k = 0; k < 8; k++) {
        int idx = tid + k * 256;             // 0..2047 over [row][il]
        int row = idx >> 4, il = idx & 15;
        out[(size_t)(gbase + row) * 32 + cb * 16 + il] = OSM[row * 17 + il];
    }
}

extern "C" void kernel_launch(void* const* d_in, const int* in_sizes, int n_in,
                              void* d_out, int out_size)
{
    const float* states = (const float*)d_in[0];  // [16, 4096, 32]
    const float* edges  = (const float*)d_in[1];  // [16, 4096, 16]
    const float* W      = (const float*)d_in[2];  // [16, 1024]
    const float* b      = (const float*)d_in[3];  // [1024]
    float* out          = (float*)d_out;          // [16, 4096, 32]

    (void)in_sizes; (void)n_in; (void)out_size;

    static int configured = 0;
    if (!configured) {
        cudaFuncSetAttribute(edge_net_mma,
                             cudaFuncAttributeMaxDynamicSharedMemorySize, SM_TOTAL);
        configured = 1;
    }
    prep_w<<<16, 256>>>(W);
    edge_net_mma<<<1024, NTHREADS, SM_TOTAL>>>(states, edges, b, out);
}